// round 15
// baseline (speedup 1.0000x reference)
#include <cuda_runtime.h>
#include <cuda_fp16.h>
#include <cstdint>

// out[b][o] = sum_k x[b][k] * W[o][k] + bias[o]
// x: (1048576,128) f32, W: (128,128) f32, bias: (128,1), out f32.
//
// R14 = R11 (165.9us best) with the CTA split into TWO independent sync
// domains via named barriers. mg-group g (threads g*128..g*128+127) stages
// and reads ONLY x rows g*32..g*32+31 of each tile; W is read-only after
// init. Groups share nothing else -> replace per-tile __syncthreads with
// bar.sync (id=1+g, 128 threads). 4 independent pipelines per SM
// (2 CTAs x 2 groups): one group's epilogue/barrier is covered by the
// other's mainloop. Register-neutral; everything else identical to R11.

#define THREADS 256
#define KDIM    128
#define TILE_B  64

// smem: x tiles [buf] 16KB at 0/16K; W at 32K..64K
#define XS_OFF(b)  ((b)*16384)
#define WS_OFF     32768
#define SMEM_BYTES 65536

// ---------------- helpers ----------------
__device__ __forceinline__ uint32_t smem_u32(const void* p) {
    uint32_t a;
    asm("{ .reg .u64 t; cvta.to.shared.u64 t, %1; cvt.u32.u64 %0, t; }" : "=r"(a) : "l"(p));
    return a;
}
__device__ __forceinline__ void sts64(uint32_t addr, uint32_t a, uint32_t b) {
    asm volatile("st.shared.v2.b32 [%0], {%1,%2};" :: "r"(addr), "r"(a), "r"(b));
}
__device__ __forceinline__ void ldsm4(uint32_t r[4], uint32_t addr) {
    asm volatile("ldmatrix.sync.aligned.m8n8.x4.shared.b16 {%0,%1,%2,%3}, [%4];"
                 : "=r"(r[0]), "=r"(r[1]), "=r"(r[2]), "=r"(r[3]) : "r"(addr));
}
__device__ __forceinline__ void hmma(float* d, const uint32_t a[4], uint32_t b0, uint32_t b1) {
    asm volatile("mma.sync.aligned.m16n8k16.row.col.f32.f16.f16.f32 "
                 "{%0,%1,%2,%3}, {%4,%5,%6,%7}, {%8,%9}, {%0,%1,%2,%3};"
                 : "+f"(d[0]), "+f"(d[1]), "+f"(d[2]), "+f"(d[3])
                 : "r"(a[0]), "r"(a[1]), "r"(a[2]), "r"(a[3]), "r"(b0), "r"(b1));
}
__device__ __forceinline__ uint32_t cvt_h2(float xx, float yy) {
    __half2 h = __float22half2_rn(make_float2(xx, yy));
    return *reinterpret_cast<uint32_t*>(&h);
}
// fp16 tile swizzle: rows x 256B, XOR on 16B granules
__device__ __forceinline__ uint32_t swz(int row, uint32_t kb) {
    return (uint32_t)row * 256u + (kb ^ (uint32_t)((row & 7) << 4));
}
// o-permutation: physical output col o -> smem B-tile row pn (see R9).
__device__ __forceinline__ int operm(int o) {
    const int ng_ = o >> 5;
    const int pr_ = (o >> 4) & 1;
    const int t_  = (o >> 2) & 3;
    const int p_  = (o >> 1) & 1;
    const int u_  = o & 1;
    return ng_ * 32 + (pr_ * 2 + p_) * 8 + t_ * 2 + u_;
}
// group-local barrier (named; ids 1,2; 128 threads each)
#define GBAR(id) asm volatile("bar.sync %0, 128;" :: "r"(id) : "memory")

// ---- staging (per group): 32 rows x 32 float4 = 1024 float4 over 128 thr ----
// idx0 = mg*1024 + (tid&127); batch j covers fidx = idx0 + (j*4+it)*128.
__device__ __forceinline__ void ldg_batch(const float4* __restrict__ src, int idx0, int j,
                                          float4 st[4]) {
    #pragma unroll
    for (int it = 0; it < 4; ++it) st[it] = __ldcs(src + idx0 + (j * 4 + it) * 128);
}
__device__ __forceinline__ void sts_batch(uint32_t xs, int idx0, int j, const float4 st[4]) {
    #pragma unroll
    for (int it = 0; it < 4; ++it) {
        int fidx = idx0 + (j * 4 + it) * 128;      // float4 index in 64x32
        int row = fidx >> 5;
        int g4  = fidx & 31;
        uint32_t off = swz(row, (uint32_t)(g4 * 8));
        sts64(xs + off, cvt_h2(st[it].x, st[it].y), cvt_h2(st[it].z, st[it].w));
    }
}

__global__ __launch_bounds__(THREADS, 2)
void linear128_f16_kernel(const float* __restrict__ x,
                          const float* __restrict__ W,
                          const float* __restrict__ bias,
                          float* __restrict__ out,
                          int ntiles)
{
    extern __shared__ __align__(1024) char smem[];
    const uint32_t sb = smem_u32(smem);
    const uint32_t ws = sb + WS_OFF;

    const int tid  = threadIdx.x;
    const int lane = tid & 31;
    const int wid  = tid >> 5;
    const int mg   = wid >> 2;   // 0..1: batch rows 32*mg == sync group
    const int ng   = wid & 3;    // 0..3: out cols 32*ng
    const int gbar = 1 + mg;     // named barrier id for this group
    const int idx0 = mg * 1024 + (tid & 127);   // staging base (own 32 rows)

    // ---- stage W (fp16) into smem with o-permutation, once ----
    {
        const float4* W4 = (const float4*)W;
        #pragma unroll
        for (int it = 0; it < 16; ++it) {
            int fidx = tid + it * THREADS;
            int o   = fidx >> 5;
            int g4  = fidx & 31;
            float4 v = W4[fidx];
            int pn = operm(o);
            sts64(ws + swz(pn, (uint32_t)(g4 * 8)),
                  cvt_h2(v.x, v.y), cvt_h2(v.z, v.w));
        }
    }

    // ---- bias: one float4 per fragment pair ----
    float4 bv[2];
    #pragma unroll
    for (int pr = 0; pr < 2; ++pr)
        bv[pr] = *(const float4*)(bias + ng * 32 + pr * 16 + (lane & 3) * 4);

    // ---- ldmatrix address components ----
    uint32_t a_ro[2], a_sw[2];
    #pragma unroll
    for (int mf = 0; mf < 2; ++mf) {
        int r = mg * 32 + mf * 16 + ((lane >> 3) & 1) * 8 + (lane & 7);
        a_ro[mf] = (uint32_t)r * 256u;
        a_sw[mf] = (uint32_t)((r & 7) << 4);
    }
    const uint32_t a_kb = (uint32_t)((lane >> 4) * 16);
    uint32_t b_ro[2], b_sw[2];
    #pragma unroll
    for (int q = 0; q < 2; ++q) {
        int r = ng * 32 + q * 16 + ((lane >> 4) << 3) + (lane & 7);
        b_ro[q] = (uint32_t)r * 256u;
        b_sw[q] = (uint32_t)((r & 7) << 4);
    }
    const uint32_t b_kb = (uint32_t)(((lane >> 3) & 1) * 16);

    const int bid  = blockIdx.x;
    const int grid = gridDim.x;
    const float4* x4 = (const float4*)x;

    // ---- prologue: stage own rows of tile(bid) into buf 0 ----
    {
        float4 st[4];
        ldg_batch(x4 + (size_t)bid * 2048, idx0, 0, st);
        sts_batch(sb + XS_OFF(0), idx0, 0, st);
        ldg_batch(x4 + (size_t)bid * 2048, idx0, 1, st);
        sts_batch(sb + XS_OFF(0), idx0, 1, st);
    }
    __syncthreads();   // one full sync: W + both groups' tile-0 staging visible

    int i = 0;
    #pragma unroll 1
    for (int tile = bid; tile < ntiles; tile += grid, ++i) {
        const uint32_t xs  = sb + XS_OFF(i & 1);
        const uint32_t nxs = sb + XS_OFF((i + 1) & 1);
        const bool hn = (tile + grid) < ntiles;
        const float4* nsrc = x4 + (size_t)(tile + grid) * 2048;

        float d[2][4][4];
        #pragma unroll
        for (int mf = 0; mf < 2; ++mf)
            #pragma unroll
            for (int nf = 0; nf < 4; ++nf)
                #pragma unroll
                for (int e = 0; e < 4; ++e) d[mf][nf][e] = 0.0f;

        float4 st0[4], st1[4];
        if (hn) ldg_batch(nsrc, idx0, 0, st0);   // reads in flight ASAP

        #pragma unroll
        for (int ks = 0; ks < 8; ++ks) {
            const uint32_t kbyte = (uint32_t)(ks * 32);
            uint32_t a[2][4];
            #pragma unroll
            for (int mf = 0; mf < 2; ++mf)
                ldsm4(a[mf], xs + a_ro[mf] + ((kbyte + a_kb) ^ a_sw[mf]));
            uint32_t b0[4], b1[4];
            #pragma unroll
            for (int q = 0; q < 2; ++q) {
                uint32_t r[4];
                ldsm4(r, ws + b_ro[q] + ((kbyte + b_kb) ^ b_sw[q]));
                b0[2*q] = r[0]; b1[2*q] = r[1]; b0[2*q+1] = r[2]; b1[2*q+1] = r[3];
            }
            #pragma unroll
            for (int mf = 0; mf < 2; ++mf)
                #pragma unroll
                for (int nf = 0; nf < 4; ++nf)
                    hmma(d[mf][nf], a[mf], b0[nf], b1[nf]);

            // reads outstanding over most of the mainloop; STS late
            if (ks == 0 && hn) { ldg_batch(nsrc, idx0, 1, st1); }
            if (ks == 4 && hn) { sts_batch(nxs, idx0, 0, st0); }
            if (ks == 6 && hn) { sts_batch(nxs, idx0, 1, st1); }
        }

        // ---- epilogue: streaming STG.128, 4 consecutive phys cols/thread ----
        #pragma unroll
        for (int mf = 0; mf < 2; ++mf) {
            const size_t rbase =
                ((size_t)tile * TILE_B + (size_t)(mg * 32 + mf * 16 + (lane >> 2))) * 128;
            #pragma unroll
            for (int pr = 0; pr < 2; ++pr) {
                const int col = ng * 32 + pr * 16 + (lane & 3) * 4;
                float4 v0, v1;
                v0.x = d[mf][2*pr][0]   + bv[pr].x;
                v0.y = d[mf][2*pr][1]   + bv[pr].y;
                v0.z = d[mf][2*pr+1][0] + bv[pr].z;
                v0.w = d[mf][2*pr+1][1] + bv[pr].w;
                v1.x = d[mf][2*pr][2]   + bv[pr].x;
                v1.y = d[mf][2*pr][3]   + bv[pr].y;
                v1.z = d[mf][2*pr+1][2] + bv[pr].z;
                v1.w = d[mf][2*pr+1][3] + bv[pr].w;
                __stcs((float4*)(out + rbase + col),           v0);
                __stcs((float4*)(out + rbase + 8 * 128 + col), v1);
            }
        }
        // group-local barrier: own rows of buf(i) fully read by own warps;
        // own staging of buf(i+1) visible to own warps. Other group untouched.
        GBAR(gbar);
    }
}

extern "C" void kernel_launch(void* const* d_in, const int* in_sizes, int n_in,
                              void* d_out, int out_size)
{
    const float* x    = (const float*)d_in[0];
    const float* W    = (const float*)d_in[1];
    const float* bias = (const float*)d_in[2];
    float* out = (float*)d_out;

    const int batch  = in_sizes[0] / KDIM;   // 1048576
    const int ntiles = batch / TILE_B;       // 16384

    int sms = 148;
    cudaDeviceGetAttribute(&sms, cudaDevAttrMultiProcessorCount, 0);
    if (sms <= 0) sms = 148;
    int grid = 2 * sms;                      // 2 CTAs per SM
    if (grid > ntiles) grid = ntiles;

    cudaFuncSetAttribute(linear128_f16_kernel,
                         cudaFuncAttributeMaxDynamicSharedMemorySize, SMEM_BYTES);

    linear128_f16_kernel<<<grid, THREADS, SMEM_BYTES>>>(x, W, bias, out, ntiles);
}

// round 16
// speedup vs baseline: 1.3075x; 1.3075x over previous
#include <cuda_runtime.h>
#include <cuda_fp16.h>
#include <cstdint>

// out[b][o] = sum_k x[b][k] * W[o][k] + bias[o]
// x: (1048576,128) f32, W: (128,128) f32, bias: (128,1), out f32.
//
// R15 = R11 (165.9us best) with ONE change: contiguous per-CTA tile chunks
// (tile in [bid*n/grid, (bid+1)*n/grid)) instead of grid-strided tiles.
// Each CTA's DRAM read and write streams become strictly sequential in
// address -> HBM row-buffer locality independent of inter-CTA drift.
// Everything else byte-identical to R11: fp16 mma, warp tile 32x32,
// 2 CTAs/SM, permuted-W STG.128 epilogue, __ldcs/__stcs, 1 sync/tile.
// (R12/R13/R14 structural variants all regressed and are reverted.)

#define THREADS 256
#define KDIM    128
#define TILE_B  64

// smem: x tiles [buf] 16KB at 0/16K; W at 32K..64K
#define XS_OFF(b)  ((b)*16384)
#define WS_OFF     32768
#define SMEM_BYTES 65536

// ---------------- helpers ----------------
__device__ __forceinline__ uint32_t smem_u32(const void* p) {
    uint32_t a;
    asm("{ .reg .u64 t; cvta.to.shared.u64 t, %1; cvt.u32.u64 %0, t; }" : "=r"(a) : "l"(p));
    return a;
}
__device__ __forceinline__ void sts64(uint32_t addr, uint32_t a, uint32_t b) {
    asm volatile("st.shared.v2.b32 [%0], {%1,%2};" :: "r"(addr), "r"(a), "r"(b));
}
__device__ __forceinline__ void ldsm4(uint32_t r[4], uint32_t addr) {
    asm volatile("ldmatrix.sync.aligned.m8n8.x4.shared.b16 {%0,%1,%2,%3}, [%4];"
                 : "=r"(r[0]), "=r"(r[1]), "=r"(r[2]), "=r"(r[3]) : "r"(addr));
}
__device__ __forceinline__ void hmma(float* d, const uint32_t a[4], uint32_t b0, uint32_t b1) {
    asm volatile("mma.sync.aligned.m16n8k16.row.col.f32.f16.f16.f32 "
                 "{%0,%1,%2,%3}, {%4,%5,%6,%7}, {%8,%9}, {%0,%1,%2,%3};"
                 : "+f"(d[0]), "+f"(d[1]), "+f"(d[2]), "+f"(d[3])
                 : "r"(a[0]), "r"(a[1]), "r"(a[2]), "r"(a[3]), "r"(b0), "r"(b1));
}
__device__ __forceinline__ uint32_t cvt_h2(float xx, float yy) {
    __half2 h = __float22half2_rn(make_float2(xx, yy));
    return *reinterpret_cast<uint32_t*>(&h);
}
// fp16 tile swizzle: rows x 256B, XOR on 16B granules
__device__ __forceinline__ uint32_t swz(int row, uint32_t kb) {
    return (uint32_t)row * 256u + (kb ^ (uint32_t)((row & 7) << 4));
}
// o-permutation: physical output col o -> smem B-tile row pn (see R9).
__device__ __forceinline__ int operm(int o) {
    const int ng_ = o >> 5;
    const int pr_ = (o >> 4) & 1;
    const int t_  = (o >> 2) & 3;
    const int p_  = (o >> 1) & 1;
    const int u_  = o & 1;
    return ng_ * 32 + (pr_ * 2 + p_) * 8 + t_ * 2 + u_;
}

// ---- staging: 64 rows x 128 f32 = 2048 float4; 4 per thread per batch ----
__device__ __forceinline__ void ldg_batch(const float4* __restrict__ src, int tid, int j,
                                          float4 st[4]) {
    #pragma unroll
    for (int it = 0; it < 4; ++it) st[it] = __ldcs(src + tid + (j * 4 + it) * THREADS);
}
__device__ __forceinline__ void sts_batch(uint32_t xs, int tid, int j, const float4 st[4]) {
    #pragma unroll
    for (int it = 0; it < 4; ++it) {
        int fidx = tid + (j * 4 + it) * THREADS;   // float4 index in 64x32
        int row = fidx >> 5;
        int g4  = fidx & 31;
        uint32_t off = swz(row, (uint32_t)(g4 * 8));
        sts64(xs + off, cvt_h2(st[it].x, st[it].y), cvt_h2(st[it].z, st[it].w));
    }
}

__global__ __launch_bounds__(THREADS, 2)
void linear128_f16_kernel(const float* __restrict__ x,
                          const float* __restrict__ W,
                          const float* __restrict__ bias,
                          float* __restrict__ out,
                          int ntiles)
{
    extern __shared__ __align__(1024) char smem[];
    const uint32_t sb = smem_u32(smem);
    const uint32_t ws = sb + WS_OFF;

    const int tid  = threadIdx.x;
    const int lane = tid & 31;
    const int wid  = tid >> 5;
    const int mg   = wid >> 2;   // 0..1: batch rows 32*mg
    const int ng   = wid & 3;    // 0..3: out cols 32*ng

    // ---- stage W (fp16) into smem with o-permutation, once ----
    {
        const float4* W4 = (const float4*)W;
        #pragma unroll
        for (int it = 0; it < 16; ++it) {
            int fidx = tid + it * THREADS;
            int o   = fidx >> 5;
            int g4  = fidx & 31;
            float4 v = W4[fidx];
            int pn = operm(o);
            sts64(ws + swz(pn, (uint32_t)(g4 * 8)),
                  cvt_h2(v.x, v.y), cvt_h2(v.z, v.w));
        }
    }

    // ---- bias: one float4 per fragment pair ----
    float4 bv[2];
    #pragma unroll
    for (int pr = 0; pr < 2; ++pr)
        bv[pr] = *(const float4*)(bias + ng * 32 + pr * 16 + (lane & 3) * 4);

    // ---- ldmatrix address components ----
    uint32_t a_ro[2], a_sw[2];
    #pragma unroll
    for (int mf = 0; mf < 2; ++mf) {
        int r = mg * 32 + mf * 16 + ((lane >> 3) & 1) * 8 + (lane & 7);
        a_ro[mf] = (uint32_t)r * 256u;
        a_sw[mf] = (uint32_t)((r & 7) << 4);
    }
    const uint32_t a_kb = (uint32_t)((lane >> 4) * 16);
    uint32_t b_ro[2], b_sw[2];
    #pragma unroll
    for (int q = 0; q < 2; ++q) {
        int r = ng * 32 + q * 16 + ((lane >> 4) << 3) + (lane & 7);
        b_ro[q] = (uint32_t)r * 256u;
        b_sw[q] = (uint32_t)((r & 7) << 4);
    }
    const uint32_t b_kb = (uint32_t)(((lane >> 3) & 1) * 16);

    const int bid  = blockIdx.x;
    const int grid = gridDim.x;
    const float4* x4 = (const float4*)x;

    // ---- contiguous tile chunk for this CTA ----
    const int t0 = (int)(((long long)bid * ntiles) / grid);
    const int t1 = (int)(((long long)(bid + 1) * ntiles) / grid);
    if (t0 >= t1) return;

    // ---- prologue: stage x tile(t0) into buf 0 ----
    {
        float4 st[4];
        ldg_batch(x4 + (size_t)t0 * 2048, tid, 0, st);
        sts_batch(sb + XS_OFF(0), tid, 0, st);
        ldg_batch(x4 + (size_t)t0 * 2048, tid, 1, st);
        sts_batch(sb + XS_OFF(0), tid, 1, st);
    }
    __syncthreads();

    int i = 0;
    #pragma unroll 1
    for (int tile = t0; tile < t1; ++tile, ++i) {
        const uint32_t xs  = sb + XS_OFF(i & 1);
        const uint32_t nxs = sb + XS_OFF((i + 1) & 1);
        const bool hn = (tile + 1) < t1;
        const float4* nsrc = x4 + (size_t)(tile + 1) * 2048;

        float d[2][4][4];
        #pragma unroll
        for (int mf = 0; mf < 2; ++mf)
            #pragma unroll
            for (int nf = 0; nf < 4; ++nf)
                #pragma unroll
                for (int e = 0; e < 4; ++e) d[mf][nf][e] = 0.0f;

        float4 st0[4], st1[4];
        if (hn) ldg_batch(nsrc, tid, 0, st0);   // issue reads ASAP after barrier

        #pragma unroll
        for (int ks = 0; ks < 8; ++ks) {
            const uint32_t kbyte = (uint32_t)(ks * 32);
            uint32_t a[2][4];
            #pragma unroll
            for (int mf = 0; mf < 2; ++mf)
                ldsm4(a[mf], xs + a_ro[mf] + ((kbyte + a_kb) ^ a_sw[mf]));
            uint32_t b0[4], b1[4];
            #pragma unroll
            for (int q = 0; q < 2; ++q) {
                uint32_t r[4];
                ldsm4(r, ws + b_ro[q] + ((kbyte + b_kb) ^ b_sw[q]));
                b0[2*q] = r[0]; b1[2*q] = r[1]; b0[2*q+1] = r[2]; b1[2*q+1] = r[3];
            }
            #pragma unroll
            for (int mf = 0; mf < 2; ++mf)
                #pragma unroll
                for (int nf = 0; nf < 4; ++nf)
                    hmma(d[mf][nf], a[mf], b0[nf], b1[nf]);

            // reads outstanding over most of the mainloop; STS late
            if (ks == 0 && hn) { ldg_batch(nsrc, tid, 1, st1); }
            if (ks == 4 && hn) { sts_batch(nxs, tid, 0, st0); }
            if (ks == 6 && hn) { sts_batch(nxs, tid, 1, st1); }
        }

        // ---- epilogue: streaming STG.128, 4 consecutive phys cols/thread ----
        #pragma unroll
        for (int mf = 0; mf < 2; ++mf) {
            const size_t rbase =
                ((size_t)tile * TILE_B + (size_t)(mg * 32 + mf * 16 + (lane >> 2))) * 128;
            #pragma unroll
            for (int pr = 0; pr < 2; ++pr) {
                const int col = ng * 32 + pr * 16 + (lane & 3) * 4;
                float4 v0, v1;
                v0.x = d[mf][2*pr][0]   + bv[pr].x;
                v0.y = d[mf][2*pr][1]   + bv[pr].y;
                v0.z = d[mf][2*pr+1][0] + bv[pr].z;
                v0.w = d[mf][2*pr+1][1] + bv[pr].w;
                v1.x = d[mf][2*pr][2]   + bv[pr].x;
                v1.y = d[mf][2*pr][3]   + bv[pr].y;
                v1.z = d[mf][2*pr+1][2] + bv[pr].z;
                v1.w = d[mf][2*pr+1][3] + bv[pr].w;
                __stcs((float4*)(out + rbase + col),           v0);
                __stcs((float4*)(out + rbase + 8 * 128 + col), v1);
            }
        }
        __syncthreads();   // buf(i) reads done; buf(i+1) staging visible
    }
}

extern "C" void kernel_launch(void* const* d_in, const int* in_sizes, int n_in,
                              void* d_out, int out_size)
{
    const float* x    = (const float*)d_in[0];
    const float* W    = (const float*)d_in[1];
    const float* bias = (const float*)d_in[2];
    float* out = (float*)d_out;

    const int batch  = in_sizes[0] / KDIM;   // 1048576
    const int ntiles = batch / TILE_B;       // 16384

    int sms = 148;
    cudaDeviceGetAttribute(&sms, cudaDevAttrMultiProcessorCount, 0);
    if (sms <= 0) sms = 148;
    int grid = 2 * sms;                      // 2 CTAs per SM
    if (grid > ntiles) grid = ntiles;

    cudaFuncSetAttribute(linear128_f16_kernel,
                         cudaFuncAttributeMaxDynamicSharedMemorySize, SMEM_BYTES);

    linear128_f16_kernel<<<grid, THREADS, SMEM_BYTES>>>(x, W, bias, out, ntiles);
}

// round 17
// speedup vs baseline: 1.3085x; 1.0007x over previous
#include <cuda_runtime.h>
#include <cuda_fp16.h>
#include <cstdint>

// out[b][o] = sum_k x[b][k] * W[o][k] + bias[o]
// x: (1048576,128) f32, W: (128,128) f32, bias: (128,1), out f32.
//
// R15 = R11 (165.9us best) with ONE change: contiguous per-CTA tile chunks
// (tile in [bid*n/grid, (bid+1)*n/grid)) instead of grid-strided tiles.
// Each CTA's DRAM read and write streams become strictly sequential in
// address -> HBM row-buffer locality independent of inter-CTA drift.
// Everything else byte-identical to R11: fp16 mma, warp tile 32x32,
// 2 CTAs/SM, permuted-W STG.128 epilogue, __ldcs/__stcs, 1 sync/tile.
// (R12/R13/R14 structural variants all regressed and are reverted.)

#define THREADS 256
#define KDIM    128
#define TILE_B  64

// smem: x tiles [buf] 16KB at 0/16K; W at 32K..64K
#define XS_OFF(b)  ((b)*16384)
#define WS_OFF     32768
#define SMEM_BYTES 65536

// ---------------- helpers ----------------
__device__ __forceinline__ uint32_t smem_u32(const void* p) {
    uint32_t a;
    asm("{ .reg .u64 t; cvta.to.shared.u64 t, %1; cvt.u32.u64 %0, t; }" : "=r"(a) : "l"(p));
    return a;
}
__device__ __forceinline__ void sts64(uint32_t addr, uint32_t a, uint32_t b) {
    asm volatile("st.shared.v2.b32 [%0], {%1,%2};" :: "r"(addr), "r"(a), "r"(b));
}
__device__ __forceinline__ void ldsm4(uint32_t r[4], uint32_t addr) {
    asm volatile("ldmatrix.sync.aligned.m8n8.x4.shared.b16 {%0,%1,%2,%3}, [%4];"
                 : "=r"(r[0]), "=r"(r[1]), "=r"(r[2]), "=r"(r[3]) : "r"(addr));
}
__device__ __forceinline__ void hmma(float* d, const uint32_t a[4], uint32_t b0, uint32_t b1) {
    asm volatile("mma.sync.aligned.m16n8k16.row.col.f32.f16.f16.f32 "
                 "{%0,%1,%2,%3}, {%4,%5,%6,%7}, {%8,%9}, {%0,%1,%2,%3};"
                 : "+f"(d[0]), "+f"(d[1]), "+f"(d[2]), "+f"(d[3])
                 : "r"(a[0]), "r"(a[1]), "r"(a[2]), "r"(a[3]), "r"(b0), "r"(b1));
}
__device__ __forceinline__ uint32_t cvt_h2(float xx, float yy) {
    __half2 h = __float22half2_rn(make_float2(xx, yy));
    return *reinterpret_cast<uint32_t*>(&h);
}
// fp16 tile swizzle: rows x 256B, XOR on 16B granules
__device__ __forceinline__ uint32_t swz(int row, uint32_t kb) {
    return (uint32_t)row * 256u + (kb ^ (uint32_t)((row & 7) << 4));
}
// o-permutation: physical output col o -> smem B-tile row pn (see R9).
__device__ __forceinline__ int operm(int o) {
    const int ng_ = o >> 5;
    const int pr_ = (o >> 4) & 1;
    const int t_  = (o >> 2) & 3;
    const int p_  = (o >> 1) & 1;
    const int u_  = o & 1;
    return ng_ * 32 + (pr_ * 2 + p_) * 8 + t_ * 2 + u_;
}

// ---- staging: 64 rows x 128 f32 = 2048 float4; 4 per thread per batch ----
__device__ __forceinline__ void ldg_batch(const float4* __restrict__ src, int tid, int j,
                                          float4 st[4]) {
    #pragma unroll
    for (int it = 0; it < 4; ++it) st[it] = __ldcs(src + tid + (j * 4 + it) * THREADS);
}
__device__ __forceinline__ void sts_batch(uint32_t xs, int tid, int j, const float4 st[4]) {
    #pragma unroll
    for (int it = 0; it < 4; ++it) {
        int fidx = tid + (j * 4 + it) * THREADS;   // float4 index in 64x32
        int row = fidx >> 5;
        int g4  = fidx & 31;
        uint32_t off = swz(row, (uint32_t)(g4 * 8));
        sts64(xs + off, cvt_h2(st[it].x, st[it].y), cvt_h2(st[it].z, st[it].w));
    }
}

__global__ __launch_bounds__(THREADS, 2)
void linear128_f16_kernel(const float* __restrict__ x,
                          const float* __restrict__ W,
                          const float* __restrict__ bias,
                          float* __restrict__ out,
                          int ntiles)
{
    extern __shared__ __align__(1024) char smem[];
    const uint32_t sb = smem_u32(smem);
    const uint32_t ws = sb + WS_OFF;

    const int tid  = threadIdx.x;
    const int lane = tid & 31;
    const int wid  = tid >> 5;
    const int mg   = wid >> 2;   // 0..1: batch rows 32*mg
    const int ng   = wid & 3;    // 0..3: out cols 32*ng

    // ---- stage W (fp16) into smem with o-permutation, once ----
    {
        const float4* W4 = (const float4*)W;
        #pragma unroll
        for (int it = 0; it < 16; ++it) {
            int fidx = tid + it * THREADS;
            int o   = fidx >> 5;
            int g4  = fidx & 31;
            float4 v = W4[fidx];
            int pn = operm(o);
            sts64(ws + swz(pn, (uint32_t)(g4 * 8)),
                  cvt_h2(v.x, v.y), cvt_h2(v.z, v.w));
        }
    }

    // ---- bias: one float4 per fragment pair ----
    float4 bv[2];
    #pragma unroll
    for (int pr = 0; pr < 2; ++pr)
        bv[pr] = *(const float4*)(bias + ng * 32 + pr * 16 + (lane & 3) * 4);

    // ---- ldmatrix address components ----
    uint32_t a_ro[2], a_sw[2];
    #pragma unroll
    for (int mf = 0; mf < 2; ++mf) {
        int r = mg * 32 + mf * 16 + ((lane >> 3) & 1) * 8 + (lane & 7);
        a_ro[mf] = (uint32_t)r * 256u;
        a_sw[mf] = (uint32_t)((r & 7) << 4);
    }
    const uint32_t a_kb = (uint32_t)((lane >> 4) * 16);
    uint32_t b_ro[2], b_sw[2];
    #pragma unroll
    for (int q = 0; q < 2; ++q) {
        int r = ng * 32 + q * 16 + ((lane >> 4) << 3) + (lane & 7);
        b_ro[q] = (uint32_t)r * 256u;
        b_sw[q] = (uint32_t)((r & 7) << 4);
    }
    const uint32_t b_kb = (uint32_t)(((lane >> 3) & 1) * 16);

    const int bid  = blockIdx.x;
    const int grid = gridDim.x;
    const float4* x4 = (const float4*)x;

    // ---- contiguous tile chunk for this CTA ----
    const int t0 = (int)(((long long)bid * ntiles) / grid);
    const int t1 = (int)(((long long)(bid + 1) * ntiles) / grid);
    if (t0 >= t1) return;

    // ---- prologue: stage x tile(t0) into buf 0 ----
    {
        float4 st[4];
        ldg_batch(x4 + (size_t)t0 * 2048, tid, 0, st);
        sts_batch(sb + XS_OFF(0), tid, 0, st);
        ldg_batch(x4 + (size_t)t0 * 2048, tid, 1, st);
        sts_batch(sb + XS_OFF(0), tid, 1, st);
    }
    __syncthreads();

    int i = 0;
    #pragma unroll 1
    for (int tile = t0; tile < t1; ++tile, ++i) {
        const uint32_t xs  = sb + XS_OFF(i & 1);
        const uint32_t nxs = sb + XS_OFF((i + 1) & 1);
        const bool hn = (tile + 1) < t1;
        const float4* nsrc = x4 + (size_t)(tile + 1) * 2048;

        float d[2][4][4];
        #pragma unroll
        for (int mf = 0; mf < 2; ++mf)
            #pragma unroll
            for (int nf = 0; nf < 4; ++nf)
                #pragma unroll
                for (int e = 0; e < 4; ++e) d[mf][nf][e] = 0.0f;

        float4 st0[4], st1[4];
        if (hn) ldg_batch(nsrc, tid, 0, st0);   // issue reads ASAP after barrier

        #pragma unroll
        for (int ks = 0; ks < 8; ++ks) {
            const uint32_t kbyte = (uint32_t)(ks * 32);
            uint32_t a[2][4];
            #pragma unroll
            for (int mf = 0; mf < 2; ++mf)
                ldsm4(a[mf], xs + a_ro[mf] + ((kbyte + a_kb) ^ a_sw[mf]));
            uint32_t b0[4], b1[4];
            #pragma unroll
            for (int q = 0; q < 2; ++q) {
                uint32_t r[4];
                ldsm4(r, ws + b_ro[q] + ((kbyte + b_kb) ^ b_sw[q]));
                b0[2*q] = r[0]; b1[2*q] = r[1]; b0[2*q+1] = r[2]; b1[2*q+1] = r[3];
            }
            #pragma unroll
            for (int mf = 0; mf < 2; ++mf)
                #pragma unroll
                for (int nf = 0; nf < 4; ++nf)
                    hmma(d[mf][nf], a[mf], b0[nf], b1[nf]);

            // reads outstanding over most of the mainloop; STS late
            if (ks == 0 && hn) { ldg_batch(nsrc, tid, 1, st1); }
            if (ks == 4 && hn) { sts_batch(nxs, tid, 0, st0); }
            if (ks == 6 && hn) { sts_batch(nxs, tid, 1, st1); }
        }

        // ---- epilogue: streaming STG.128, 4 consecutive phys cols/thread ----
        #pragma unroll
        for (int mf = 0; mf < 2; ++mf) {
            const size_t rbase =
                ((size_t)tile * TILE_B + (size_t)(mg * 32 + mf * 16 + (lane >> 2))) * 128;
            #pragma unroll
            for (int pr = 0; pr < 2; ++pr) {
                const int col = ng * 32 + pr * 16 + (lane & 3) * 4;
                float4 v0, v1;
                v0.x = d[mf][2*pr][0]   + bv[pr].x;
                v0.y = d[mf][2*pr][1]   + bv[pr].y;
                v0.z = d[mf][2*pr+1][0] + bv[pr].z;
                v0.w = d[mf][2*pr+1][1] + bv[pr].w;
                v1.x = d[mf][2*pr][2]   + bv[pr].x;
                v1.y = d[mf][2*pr][3]   + bv[pr].y;
                v1.z = d[mf][2*pr+1][2] + bv[pr].z;
                v1.w = d[mf][2*pr+1][3] + bv[pr].w;
                __stcs((float4*)(out + rbase + col),           v0);
                __stcs((float4*)(out + rbase + 8 * 128 + col), v1);
            }
        }
        __syncthreads();   // buf(i) reads done; buf(i+1) staging visible
    }
}

extern "C" void kernel_launch(void* const* d_in, const int* in_sizes, int n_in,
                              void* d_out, int out_size)
{
    const float* x    = (const float*)d_in[0];
    const float* W    = (const float*)d_in[1];
    const float* bias = (const float*)d_in[2];
    float* out = (float*)d_out;

    const int batch  = in_sizes[0] / KDIM;   // 1048576
    const int ntiles = batch / TILE_B;       // 16384

    int sms = 148;
    cudaDeviceGetAttribute(&sms, cudaDevAttrMultiProcessorCount, 0);
    if (sms <= 0) sms = 148;
    int grid = 2 * sms;                      // 2 CTAs per SM
    if (grid > ntiles) grid = ntiles;

    cudaFuncSetAttribute(linear128_f16_kernel,
                         cudaFuncAttributeMaxDynamicSharedMemorySize, SMEM_BYTES);

    linear128_f16_kernel<<<grid, THREADS, SMEM_BYTES>>>(x, W, bias, out, ntiles);
}